// round 2
// baseline (speedup 1.0000x reference)
#include <cuda_runtime.h>
#include <math.h>

#define BB      32
#define DIMM    4096
#define NH      32
#define NKV     8
#define HD      128
#define TSEQ    2048
#define NSPLIT  8
#define CHUNK   256      /* TSEQ / NSPLIT */
#define QK_SCALE 0.08838834764831845f  /* 128^-0.5 */

// ------------------------- scratch (device globals) -------------------------
__device__ float g_q[BB * NH * HD];            // roped Q   [b][h][d]
__device__ float g_k[BB * NKV * HD];           // roped K @ pos 2047 [b][kv][d]
__device__ float g_v[BB * NKV * HD];           // V       @ pos 2047 [b][kv][d]
__device__ float g_att[BB * DIMM];             // attention output [b][h*128+d]
__device__ float g_part[BB * NH * NSPLIT * HD];
__device__ float g_ml[BB * NH * NSPLIT * 2];   // (m, l) per split

// ---------------------------------------------------------------------------
// GEMM: out[m][n] = sum_k x[m][k] * w[n][k];  M = 32 (batch), K = 4096.
// Block = 128 threads (4 warps), 16 columns per block, 4 per warp.
// Lanes span k (coalesced 512B weight loads from global; weights have no
// reuse beyond the 32 batch rows, so no smem staging for w).
// x staged in smem tiles of 256 k (32 KB). Register tile: float4 acc[32]
// (m-index × 4 columns). Cross-lane k-reduction via log-step shuffle
// halving: lane l ends holding the full sums for batch m = l.
// MODE 0: fused QKV + RoPE epilogue -> g_q / g_k / g_v
// MODE 1: x = g_att, w = wo, plain write to out
// ---------------------------------------------------------------------------
template <int MODE>
__global__ __launch_bounds__(128) void gemm_kernel(
    const float* __restrict__ x,
    const float* __restrict__ wq, const float* __restrict__ wk,
    const float* __restrict__ wv,
    const float* __restrict__ fc, const float* __restrict__ fs,
    float* __restrict__ out)
{
    __shared__ float4 xs4[32 * 64];   // 32 KB: x tile [m][256k]

    const int tid  = threadIdx.x;
    const int lane = tid & 31;
    const int warp = tid >> 5;
    const int nblk = blockIdx.x * 16;
    const int n0   = nblk + warp * 4;

    const float* w;
    int nrel;
    if (MODE == 0) {
        if (nblk < 4096)      { w = wq; nrel = n0; }
        else if (nblk < 5120) { w = wk; nrel = n0 - 4096; }
        else                  { w = wv; nrel = n0 - 5120; }
    } else { w = wq; nrel = n0; }

    const float4* w0 = (const float4*)(w + (size_t)(nrel + 0) * 4096);
    const float4* w1 = (const float4*)(w + (size_t)(nrel + 1) * 4096);
    const float4* w2 = (const float4*)(w + (size_t)(nrel + 2) * 4096);
    const float4* w3 = (const float4*)(w + (size_t)(nrel + 3) * 4096);
    const float4* xg = (const float4*)((MODE == 1) ? (const float*)g_att : x);

    float4 acc[32];
#pragma unroll
    for (int m = 0; m < 32; m++) acc[m] = make_float4(0.f, 0.f, 0.f, 0.f);

    for (int tile = 0; tile < 16; ++tile) {
        __syncthreads();
#pragma unroll
        for (int j = 0; j < 16; j++) {
            int idx = tid + j * 128;            // 0..2047 float4s
            int m   = idx >> 6;
            int kk  = idx & 63;
            xs4[idx] = xg[m * 1024 + tile * 64 + kk];
        }
        __syncthreads();
#pragma unroll
        for (int r = 0; r < 2; r++) {
            int ki = tile * 64 + r * 32 + lane;
            float4 a = w0[ki], b = w1[ki], c = w2[ki], d = w3[ki];
#pragma unroll
            for (int m = 0; m < 32; m++) {
                float4 xv = xs4[m * 64 + r * 32 + lane];
                acc[m].x = fmaf(xv.x, a.x, fmaf(xv.y, a.y, fmaf(xv.z, a.z, fmaf(xv.w, a.w, acc[m].x))));
                acc[m].y = fmaf(xv.x, b.x, fmaf(xv.y, b.y, fmaf(xv.z, b.z, fmaf(xv.w, b.w, acc[m].y))));
                acc[m].z = fmaf(xv.x, c.x, fmaf(xv.y, c.y, fmaf(xv.z, c.z, fmaf(xv.w, c.w, acc[m].z))));
                acc[m].w = fmaf(xv.x, d.x, fmaf(xv.y, d.y, fmaf(xv.z, d.z, fmaf(xv.w, d.w, acc[m].w))));
            }
        }
    }

    // in-place log-step shuffle reduction: lane l -> totals for m = l
#pragma unroll
    for (int step = 16; step >= 1; step >>= 1) {
        bool hi = (lane & step) != 0;
#pragma unroll
        for (int i = 0; i < step; i++) {
            float4 s = hi ? acc[i] : acc[i + step];
            float4 k = hi ? acc[i + step] : acc[i];
            float4 r;
            r.x = k.x + __shfl_xor_sync(0xffffffffu, s.x, step);
            r.y = k.y + __shfl_xor_sync(0xffffffffu, s.y, step);
            r.z = k.z + __shfl_xor_sync(0xffffffffu, s.z, step);
            r.w = k.w + __shfl_xor_sync(0xffffffffu, s.w, step);
            acc[i] = r;
        }
    }
    float4 res = acc[0];   // columns n0..n0+3 for batch m = lane
    const int m = lane;

    if (MODE == 1) {
        float* o = out + (size_t)m * 4096 + n0;
        o[0] = res.x; o[1] = res.y; o[2] = res.z; o[3] = res.w;
    } else {
        if (n0 < 4096) {            // Q + RoPE
            int h = n0 >> 7, d = n0 & 127;
            int i0 = d >> 1;
            float c0 = fc[i0], s0 = fs[i0], c1 = fc[i0 + 1], s1 = fs[i0 + 1];
            float* o = &g_q[(m * NH + h) * HD + d];
            o[0] = res.x * c0 - res.y * s0;
            o[1] = res.x * s0 + res.y * c0;
            o[2] = res.z * c1 - res.w * s1;
            o[3] = res.z * s1 + res.w * c1;
        } else if (n0 < 5120) {     // K + RoPE
            int nk = n0 - 4096;
            int h = nk >> 7, d = nk & 127;
            int i0 = d >> 1;
            float c0 = fc[i0], s0 = fs[i0], c1 = fc[i0 + 1], s1 = fs[i0 + 1];
            float* o = &g_k[(m * NKV + h) * HD + d];
            o[0] = res.x * c0 - res.y * s0;
            o[1] = res.x * s0 + res.y * c0;
            o[2] = res.z * c1 - res.w * s1;
            o[3] = res.z * s1 + res.w * c1;
        } else {                    // V passthrough
            int nv = n0 - 5120;
            int h = nv >> 7, d = nv & 127;
            float* o = &g_v[(m * NKV + h) * HD + d];
            o[0] = res.x; o[1] = res.y; o[2] = res.z; o[3] = res.w;
        }
    }
}

// ---------------------------------------------------------------------------
// Split-sequence flash decode. Grid = B*NKV*NSPLIT blocks of 256 threads.
// Each block: 4 rep-heads x 256 positions. Position 2047 comes from the
// freshly roped g_k/g_v (cache row 2047 is stale garbage).
// ---------------------------------------------------------------------------
__global__ __launch_bounds__(256) void attn_kernel(
    const float* __restrict__ ck, const float* __restrict__ cv)
{
    __shared__ float s_sc[4 * CHUNK];
    __shared__ float s_ml[8];

    const int bid   = blockIdx.x;
    const int split = bid % NSPLIT;
    const int kv    = (bid / NSPLIT) % NKV;
    const int b     = bid / (NSPLIT * NKV);
    const int tid   = threadIdx.x;
    const int lane  = tid & 31;
    const int warp  = tid >> 5;
    const int t0    = split * CHUNK;
    const bool last = (split == NSPLIT - 1);
    const int nmain = last ? CHUNK - 1 : CHUNK;

    // ---- phase 1: scores (warp per position, lanes span d) ----
    const float4* qg = (const float4*)g_q;
    const int qb = (b * NH + kv * 4) * 32;
    float4 q0 = qg[qb + 0 * 32 + lane];
    float4 q1 = qg[qb + 1 * 32 + lane];
    float4 q2 = qg[qb + 2 * 32 + lane];
    float4 q3 = qg[qb + 3 * 32 + lane];

    const float4* kg = (const float4*)ck + (size_t)(b * TSEQ + t0) * (NKV * 32) + kv * 32 + lane;
    for (int i = warp; i < nmain; i += 8) {
        float4 k4 = kg[(size_t)i * (NKV * 32)];
        float s0 = q0.x * k4.x + q0.y * k4.y + q0.z * k4.z + q0.w * k4.w;
        float s1 = q1.x * k4.x + q1.y * k4.y + q1.z * k4.z + q1.w * k4.w;
        float s2 = q2.x * k4.x + q2.y * k4.y + q2.z * k4.z + q2.w * k4.w;
        float s3 = q3.x * k4.x + q3.y * k4.y + q3.z * k4.z + q3.w * k4.w;
#pragma unroll
        for (int o = 16; o; o >>= 1) {
            s0 += __shfl_xor_sync(0xffffffffu, s0, o);
            s1 += __shfl_xor_sync(0xffffffffu, s1, o);
            s2 += __shfl_xor_sync(0xffffffffu, s2, o);
            s3 += __shfl_xor_sync(0xffffffffu, s3, o);
        }
        if (lane == 0) {
            s_sc[0 * CHUNK + i] = s0 * QK_SCALE;
            s_sc[1 * CHUNK + i] = s1 * QK_SCALE;
            s_sc[2 * CHUNK + i] = s2 * QK_SCALE;
            s_sc[3 * CHUNK + i] = s3 * QK_SCALE;
        }
    }
    if (last && warp == 7) {   // position 2047 from roped scratch
        const float4* kg2 = (const float4*)g_k;
        float4 k4 = kg2[(b * NKV + kv) * 32 + lane];
        float s0 = q0.x * k4.x + q0.y * k4.y + q0.z * k4.z + q0.w * k4.w;
        float s1 = q1.x * k4.x + q1.y * k4.y + q1.z * k4.z + q1.w * k4.w;
        float s2 = q2.x * k4.x + q2.y * k4.y + q2.z * k4.z + q2.w * k4.w;
        float s3 = q3.x * k4.x + q3.y * k4.y + q3.z * k4.z + q3.w * k4.w;
#pragma unroll
        for (int o = 16; o; o >>= 1) {
            s0 += __shfl_xor_sync(0xffffffffu, s0, o);
            s1 += __shfl_xor_sync(0xffffffffu, s1, o);
            s2 += __shfl_xor_sync(0xffffffffu, s2, o);
            s3 += __shfl_xor_sync(0xffffffffu, s3, o);
        }
        if (lane == 0) {
            s_sc[0 * CHUNK + CHUNK - 1] = s0 * QK_SCALE;
            s_sc[1 * CHUNK + CHUNK - 1] = s1 * QK_SCALE;
            s_sc[2 * CHUNK + CHUNK - 1] = s2 * QK_SCALE;
            s_sc[3 * CHUNK + CHUNK - 1] = s3 * QK_SCALE;
        }
    }
    __syncthreads();

    // ---- phase 2: local softmax (warp r handles row r) ----
    if (warp < 4) {
        float* row = s_sc + warp * CHUNK;
        float v[8];
        float mx = -1e30f;
#pragma unroll
        for (int j = 0; j < 8; j++) { v[j] = row[lane + 32 * j]; mx = fmaxf(mx, v[j]); }
#pragma unroll
        for (int o = 16; o; o >>= 1) mx = fmaxf(mx, __shfl_xor_sync(0xffffffffu, mx, o));
        float sum = 0.f;
#pragma unroll
        for (int j = 0; j < 8; j++) {
            float p = __expf(v[j] - mx);
            row[lane + 32 * j] = p;
            sum += p;
        }
#pragma unroll
        for (int o = 16; o; o >>= 1) sum += __shfl_xor_sync(0xffffffffu, sum, o);
        if (lane == 0) { s_ml[warp * 2] = mx; s_ml[warp * 2 + 1] = sum; }
    }
    __syncthreads();

    // ---- phase 3: P @ V (thread per (r-pair, d)) ----
    const int rg = tid >> 7;    // 0 or 1 -> heads {0,1} or {2,3}
    const int d  = tid & 127;
    float a0 = 0.f, a1 = 0.f;
    const float* vbase = cv + (size_t)((b * TSEQ + t0) * NKV + kv) * HD + d;
    const float* p0r = s_sc + (2 * rg) * CHUNK;
    const float* p1r = s_sc + (2 * rg + 1) * CHUNK;
#pragma unroll 4
    for (int i = 0; i < nmain; i++) {
        float vv = vbase[(size_t)i * (NKV * HD)];
        a0 = fmaf(p0r[i], vv, a0);
        a1 = fmaf(p1r[i], vv, a1);
    }
    if (last) {
        float vv = g_v[(b * NKV + kv) * HD + d];
        a0 = fmaf(p0r[CHUNK - 1], vv, a0);
        a1 = fmaf(p1r[CHUNK - 1], vv, a1);
    }
    const int hg0 = b * NH + kv * 4 + 2 * rg;
    g_part[((size_t)hg0 * NSPLIT + split) * HD + d]       = a0;
    g_part[((size_t)(hg0 + 1) * NSPLIT + split) * HD + d] = a1;
    if (tid < 8) {
        int r = tid >> 1;
        g_ml[((b * NH + kv * 4 + r) * NSPLIT + split) * 2 + (tid & 1)] = s_ml[tid];
    }
}

// ---------------------------------------------------------------------------
// Combine split partials (log-sum-exp). Grid = B*NH blocks of 128 threads.
// ---------------------------------------------------------------------------
__global__ __launch_bounds__(128) void reduce_kernel()
{
    const int hg = blockIdx.x;        // b*NH + h
    const int d  = threadIdx.x;
    float ms[NSPLIT], ls[NSPLIT];
    float m = -1e30f;
#pragma unroll
    for (int i = 0; i < NSPLIT; i++) {
        ms[i] = g_ml[(hg * NSPLIT + i) * 2];
        ls[i] = g_ml[(hg * NSPLIT + i) * 2 + 1];
        m = fmaxf(m, ms[i]);
    }
    float num = 0.f, den = 0.f;
#pragma unroll
    for (int i = 0; i < NSPLIT; i++) {
        float wgt = __expf(ms[i] - m);
        den += wgt * ls[i];
        num += wgt * g_part[((size_t)hg * NSPLIT + i) * HD + d];
    }
    const int b = hg >> 5, h = hg & 31;
    g_att[b * DIMM + h * HD + d] = num / den;
}

// ---------------------------------------------------------------------------
extern "C" void kernel_launch(void* const* d_in, const int* in_sizes, int n_in,
                              void* d_out, int out_size)
{
    const float* x  = (const float*)d_in[0];
    const float* fc = (const float*)d_in[1];
    const float* fs = (const float*)d_in[2];
    const float* wq = (const float*)d_in[3];
    const float* wk = (const float*)d_in[4];
    const float* wv = (const float*)d_in[5];
    const float* wo = (const float*)d_in[6];
    const float* ck = (const float*)d_in[7];
    const float* cv = (const float*)d_in[8];
    float* out = (float*)d_out;

    gemm_kernel<0><<<6144 / 16, 128>>>(x, wq, wk, wv, fc, fs, nullptr);
    attn_kernel<<<BB * NKV * NSPLIT, 256>>>(ck, cv);
    reduce_kernel<<<BB * NH, 128>>>();
    gemm_kernel<1><<<4096 / 16, 128>>>(nullptr, wo, nullptr, nullptr, nullptr, nullptr, out);
}

// round 3
// speedup vs baseline: 1.0540x; 1.0540x over previous
#include <cuda_runtime.h>
#include <math.h>

#define BB      32
#define DIMM    4096
#define NH      32
#define NKV     8
#define HD      128
#define TSEQ    2048
#define NSPLIT  8
#define CHUNK   256      /* TSEQ / NSPLIT */
#define QK_SCALE 0.08838834764831845f  /* 128^-0.5 */

// ------------------------- scratch (device globals) -------------------------
__device__ float g_q[BB * NH * HD];            // roped Q   [b][h][d]
__device__ float g_k[BB * NKV * HD];           // roped K @ pos 2047 [b][kv][d]
__device__ float g_v[BB * NKV * HD];           // V       @ pos 2047 [b][kv][d]
__device__ float g_att[BB * DIMM];             // attention output [b][h*128+d]
__device__ float g_part[BB * NH * NSPLIT * HD];
__device__ float g_ml[BB * NH * NSPLIT * 2];   // (m, l) per split

// ---------------------------------------------------------------------------
// GEMM: out[m][n] = sum_k x[m][k] * w[n][k];  M = 32 (batch), K = 4096.
// (unchanged from R2 — attn is this round's target)
// ---------------------------------------------------------------------------
template <int MODE>
__global__ __launch_bounds__(128) void gemm_kernel(
    const float* __restrict__ x,
    const float* __restrict__ wq, const float* __restrict__ wk,
    const float* __restrict__ wv,
    const float* __restrict__ fc, const float* __restrict__ fs,
    float* __restrict__ out)
{
    __shared__ float4 xs4[32 * 64];   // 32 KB: x tile [m][256k]

    const int tid  = threadIdx.x;
    const int lane = tid & 31;
    const int warp = tid >> 5;
    const int nblk = blockIdx.x * 16;
    const int n0   = nblk + warp * 4;

    const float* w;
    int nrel;
    if (MODE == 0) {
        if (nblk < 4096)      { w = wq; nrel = n0; }
        else if (nblk < 5120) { w = wk; nrel = n0 - 4096; }
        else                  { w = wv; nrel = n0 - 5120; }
    } else { w = wq; nrel = n0; }

    const float4* w0 = (const float4*)(w + (size_t)(nrel + 0) * 4096);
    const float4* w1 = (const float4*)(w + (size_t)(nrel + 1) * 4096);
    const float4* w2 = (const float4*)(w + (size_t)(nrel + 2) * 4096);
    const float4* w3 = (const float4*)(w + (size_t)(nrel + 3) * 4096);
    const float4* xg = (const float4*)((MODE == 1) ? (const float*)g_att : x);

    float4 acc[32];
#pragma unroll
    for (int m = 0; m < 32; m++) acc[m] = make_float4(0.f, 0.f, 0.f, 0.f);

    for (int tile = 0; tile < 16; ++tile) {
        __syncthreads();
#pragma unroll
        for (int j = 0; j < 16; j++) {
            int idx = tid + j * 128;            // 0..2047 float4s
            int m   = idx >> 6;
            int kk  = idx & 63;
            xs4[idx] = xg[m * 1024 + tile * 64 + kk];
        }
        __syncthreads();
#pragma unroll
        for (int r = 0; r < 2; r++) {
            int ki = tile * 64 + r * 32 + lane;
            float4 a = w0[ki], b = w1[ki], c = w2[ki], d = w3[ki];
#pragma unroll
            for (int m = 0; m < 32; m++) {
                float4 xv = xs4[m * 64 + r * 32 + lane];
                acc[m].x = fmaf(xv.x, a.x, fmaf(xv.y, a.y, fmaf(xv.z, a.z, fmaf(xv.w, a.w, acc[m].x))));
                acc[m].y = fmaf(xv.x, b.x, fmaf(xv.y, b.y, fmaf(xv.z, b.z, fmaf(xv.w, b.w, acc[m].y))));
                acc[m].z = fmaf(xv.x, c.x, fmaf(xv.y, c.y, fmaf(xv.z, c.z, fmaf(xv.w, c.w, acc[m].z))));
                acc[m].w = fmaf(xv.x, d.x, fmaf(xv.y, d.y, fmaf(xv.z, d.z, fmaf(xv.w, d.w, acc[m].w))));
            }
        }
    }

    // in-place log-step shuffle reduction: lane l -> totals for m = l
#pragma unroll
    for (int step = 16; step >= 1; step >>= 1) {
        bool hi = (lane & step) != 0;
#pragma unroll
        for (int i = 0; i < step; i++) {
            float4 s = hi ? acc[i] : acc[i + step];
            float4 k = hi ? acc[i + step] : acc[i];
            float4 r;
            r.x = k.x + __shfl_xor_sync(0xffffffffu, s.x, step);
            r.y = k.y + __shfl_xor_sync(0xffffffffu, s.y, step);
            r.z = k.z + __shfl_xor_sync(0xffffffffu, s.z, step);
            r.w = k.w + __shfl_xor_sync(0xffffffffu, s.w, step);
            acc[i] = r;
        }
    }
    float4 res = acc[0];   // columns n0..n0+3 for batch m = lane
    const int m = lane;

    if (MODE == 1) {
        float* o = out + (size_t)m * 4096 + n0;
        o[0] = res.x; o[1] = res.y; o[2] = res.z; o[3] = res.w;
    } else {
        if (n0 < 4096) {            // Q + RoPE
            int h = n0 >> 7, d = n0 & 127;
            int i0 = d >> 1;
            float c0 = fc[i0], s0 = fs[i0], c1 = fc[i0 + 1], s1 = fs[i0 + 1];
            float* o = &g_q[(m * NH + h) * HD + d];
            o[0] = res.x * c0 - res.y * s0;
            o[1] = res.x * s0 + res.y * c0;
            o[2] = res.z * c1 - res.w * s1;
            o[3] = res.z * s1 + res.w * c1;
        } else if (n0 < 5120) {     // K + RoPE
            int nk = n0 - 4096;
            int h = nk >> 7, d = nk & 127;
            int i0 = d >> 1;
            float c0 = fc[i0], s0 = fs[i0], c1 = fc[i0 + 1], s1 = fs[i0 + 1];
            float* o = &g_k[(m * NKV + h) * HD + d];
            o[0] = res.x * c0 - res.y * s0;
            o[1] = res.x * s0 + res.y * c0;
            o[2] = res.z * c1 - res.w * s1;
            o[3] = res.z * s1 + res.w * c1;
        } else {                    // V passthrough
            int nv = n0 - 5120;
            int h = nv >> 7, d = nv & 127;
            float* o = &g_v[(m * NKV + h) * HD + d];
            o[0] = res.x; o[1] = res.y; o[2] = res.z; o[3] = res.w;
        }
    }
}

// ---------------------------------------------------------------------------
// Split-sequence flash decode. Grid = B*NKV*NSPLIT blocks of 256 threads.
// Phase 1: warp processes 4 positions per iteration (4 independent LDG.128
//   up front -> MLP 4; 16 overlapping shuffle-reduction chains).
// Phase 3: thread = (pos-group = warp, d-quad = lane); float4 V loads
//   (coalesced 512B/warp/iter), 4 packed accumulators, smem cross-group
//   reduction at the end.
// Position 2047 comes from the freshly roped g_k/g_v (cache row is stale).
// ---------------------------------------------------------------------------
__global__ __launch_bounds__(256) void attn_kernel(
    const float* __restrict__ ck, const float* __restrict__ cv)
{
    __shared__ float  s_sc[4 * CHUNK];     // 4 KB: scores -> exp(p)
    __shared__ float  s_ml[8];
    __shared__ float4 s_red[8 * 4 * 32];   // 16 KB: [pg][h][dquad]

    const int bid   = blockIdx.x;
    const int split = bid % NSPLIT;
    const int kv    = (bid / NSPLIT) % NKV;
    const int b     = bid / (NSPLIT * NKV);
    const int tid   = threadIdx.x;
    const int lane  = tid & 31;
    const int warp  = tid >> 5;
    const int t0    = split * CHUNK;
    const bool last = (split == NSPLIT - 1);
    const int nmain = last ? CHUNK - 1 : CHUNK;

    // ---- phase 1: scores; warp handles 4 positions per outer iteration ----
    const float4* qg = (const float4*)g_q;
    const int qb = (b * NH + kv * 4) * 32;
    float4 q0 = qg[qb + 0 * 32 + lane];
    float4 q1 = qg[qb + 1 * 32 + lane];
    float4 q2 = qg[qb + 2 * 32 + lane];
    float4 q3 = qg[qb + 3 * 32 + lane];

    const float4* kg = (const float4*)ck
                     + (size_t)(b * TSEQ + t0) * (NKV * 32) + kv * 32 + lane;
#pragma unroll 2
    for (int base = warp * 4; base < CHUNK; base += 32) {
        float4 k4[4];
#pragma unroll
        for (int j = 0; j < 4; j++)       // rows 0..255 of this split all exist
            k4[j] = kg[(size_t)(base + j) * (NKV * 32)];

        float s[16];
#pragma unroll
        for (int j = 0; j < 4; j++) {
            s[j*4+0] = fmaf(k4[j].x, q0.x, fmaf(k4[j].y, q0.y, fmaf(k4[j].z, q0.z, k4[j].w * q0.w)));
            s[j*4+1] = fmaf(k4[j].x, q1.x, fmaf(k4[j].y, q1.y, fmaf(k4[j].z, q1.z, k4[j].w * q1.w)));
            s[j*4+2] = fmaf(k4[j].x, q2.x, fmaf(k4[j].y, q2.y, fmaf(k4[j].z, q2.z, k4[j].w * q2.w)));
            s[j*4+3] = fmaf(k4[j].x, q3.x, fmaf(k4[j].y, q3.y, fmaf(k4[j].z, q3.z, k4[j].w * q3.w)));
        }
#pragma unroll
        for (int o = 16; o; o >>= 1) {
#pragma unroll
            for (int v = 0; v < 16; v++)
                s[v] += __shfl_xor_sync(0xffffffffu, s[v], o);
        }
        if (lane == 0) {
#pragma unroll
            for (int j = 0; j < 4; j++) {
                if (base + j < nmain) {
                    s_sc[0 * CHUNK + base + j] = s[j*4+0] * QK_SCALE;
                    s_sc[1 * CHUNK + base + j] = s[j*4+1] * QK_SCALE;
                    s_sc[2 * CHUNK + base + j] = s[j*4+2] * QK_SCALE;
                    s_sc[3 * CHUNK + base + j] = s[j*4+3] * QK_SCALE;
                }
            }
        }
    }
    if (last && warp == 7) {   // position 2047 from roped scratch
        const float4* kg2 = (const float4*)g_k;
        float4 k4 = kg2[(b * NKV + kv) * 32 + lane];
        float s0 = q0.x * k4.x + q0.y * k4.y + q0.z * k4.z + q0.w * k4.w;
        float s1 = q1.x * k4.x + q1.y * k4.y + q1.z * k4.z + q1.w * k4.w;
        float s2 = q2.x * k4.x + q2.y * k4.y + q2.z * k4.z + q2.w * k4.w;
        float s3 = q3.x * k4.x + q3.y * k4.y + q3.z * k4.z + q3.w * k4.w;
#pragma unroll
        for (int o = 16; o; o >>= 1) {
            s0 += __shfl_xor_sync(0xffffffffu, s0, o);
            s1 += __shfl_xor_sync(0xffffffffu, s1, o);
            s2 += __shfl_xor_sync(0xffffffffu, s2, o);
            s3 += __shfl_xor_sync(0xffffffffu, s3, o);
        }
        if (lane == 0) {
            s_sc[0 * CHUNK + CHUNK - 1] = s0 * QK_SCALE;
            s_sc[1 * CHUNK + CHUNK - 1] = s1 * QK_SCALE;
            s_sc[2 * CHUNK + CHUNK - 1] = s2 * QK_SCALE;
            s_sc[3 * CHUNK + CHUNK - 1] = s3 * QK_SCALE;
        }
    }
    __syncthreads();

    // ---- phase 2: local softmax (warp r handles row r) ----
    if (warp < 4) {
        float* row = s_sc + warp * CHUNK;
        float v[8];
        float mx = -1e30f;
#pragma unroll
        for (int j = 0; j < 8; j++) { v[j] = row[lane + 32 * j]; mx = fmaxf(mx, v[j]); }
#pragma unroll
        for (int o = 16; o; o >>= 1) mx = fmaxf(mx, __shfl_xor_sync(0xffffffffu, mx, o));
        float sum = 0.f;
#pragma unroll
        for (int j = 0; j < 8; j++) {
            float p = __expf(v[j] - mx);
            row[lane + 32 * j] = p;
            sum += p;
        }
#pragma unroll
        for (int o = 16; o; o >>= 1) sum += __shfl_xor_sync(0xffffffffu, sum, o);
        if (lane == 0) { s_ml[warp * 2] = mx; s_ml[warp * 2 + 1] = sum; }
    }
    __syncthreads();

    // ---- phase 3: P @ V ----
    // warp = pos-group (positions warp, warp+8, ...), lane = d-quad.
    {
        const int pg = warp;
        const int dq = lane;
        float4 a0 = make_float4(0.f,0.f,0.f,0.f);
        float4 a1 = a0, a2 = a0, a3 = a0;
        const float4* vb = (const float4*)cv
                         + (size_t)(b * TSEQ + t0) * (NKV * 32) + kv * 32 + dq;
        const float* p0r = s_sc + 0 * CHUNK;
        const float* p1r = s_sc + 1 * CHUNK;
        const float* p2r = s_sc + 2 * CHUNK;
        const float* p3r = s_sc + 3 * CHUNK;
#pragma unroll 4
        for (int i = pg; i < nmain; i += 8) {
            float4 v4 = vb[(size_t)i * (NKV * 32)];
            float p0 = p0r[i], p1 = p1r[i], p2 = p2r[i], p3 = p3r[i];
            a0.x = fmaf(p0, v4.x, a0.x); a0.y = fmaf(p0, v4.y, a0.y);
            a0.z = fmaf(p0, v4.z, a0.z); a0.w = fmaf(p0, v4.w, a0.w);
            a1.x = fmaf(p1, v4.x, a1.x); a1.y = fmaf(p1, v4.y, a1.y);
            a1.z = fmaf(p1, v4.z, a1.z); a1.w = fmaf(p1, v4.w, a1.w);
            a2.x = fmaf(p2, v4.x, a2.x); a2.y = fmaf(p2, v4.y, a2.y);
            a2.z = fmaf(p2, v4.z, a2.z); a2.w = fmaf(p2, v4.w, a2.w);
            a3.x = fmaf(p3, v4.x, a3.x); a3.y = fmaf(p3, v4.y, a3.y);
            a3.z = fmaf(p3, v4.z, a3.z); a3.w = fmaf(p3, v4.w, a3.w);
        }
        s_red[(pg * 4 + 0) * 32 + dq] = a0;
        s_red[(pg * 4 + 1) * 32 + dq] = a1;
        s_red[(pg * 4 + 2) * 32 + dq] = a2;
        s_red[(pg * 4 + 3) * 32 + dq] = a3;
    }
    __syncthreads();

    // cross-pos-group reduction + last-position term; 128 threads, one
    // (head, dquad) each.
    if (tid < 128) {
        const int h  = tid >> 5;
        const int dq = tid & 31;
        float4 s = make_float4(0.f, 0.f, 0.f, 0.f);
#pragma unroll
        for (int pg = 0; pg < 8; pg++) {
            float4 t = s_red[(pg * 4 + h) * 32 + dq];
            s.x += t.x; s.y += t.y; s.z += t.z; s.w += t.w;
        }
        if (last) {
            float4 v4 = ((const float4*)g_v)[(b * NKV + kv) * 32 + dq];
            float p = s_sc[h * CHUNK + CHUNK - 1];
            s.x = fmaf(p, v4.x, s.x); s.y = fmaf(p, v4.y, s.y);
            s.z = fmaf(p, v4.z, s.z); s.w = fmaf(p, v4.w, s.w);
        }
        float4* gp = (float4*)g_part;
        gp[((size_t)(b * NH + kv * 4 + h) * NSPLIT + split) * 32 + dq] = s;
    }
    if (tid < 8) {
        int r = tid >> 1;
        g_ml[((b * NH + kv * 4 + r) * NSPLIT + split) * 2 + (tid & 1)] = s_ml[tid];
    }
}

// ---------------------------------------------------------------------------
// Combine split partials (log-sum-exp). Grid = B*NH blocks of 128 threads.
// ---------------------------------------------------------------------------
__global__ __launch_bounds__(128) void reduce_kernel()
{
    const int hg = blockIdx.x;        // b*NH + h
    const int d  = threadIdx.x;
    float ms[NSPLIT], ls[NSPLIT];
    float m = -1e30f;
#pragma unroll
    for (int i = 0; i < NSPLIT; i++) {
        ms[i] = g_ml[(hg * NSPLIT + i) * 2];
        ls[i] = g_ml[(hg * NSPLIT + i) * 2 + 1];
        m = fmaxf(m, ms[i]);
    }
    float num = 0.f, den = 0.f;
#pragma unroll
    for (int i = 0; i < NSPLIT; i++) {
        float wgt = __expf(ms[i] - m);
        den += wgt * ls[i];
        num += wgt * g_part[((size_t)hg * NSPLIT + i) * HD + d];
    }
    const int b = hg >> 5, h = hg & 31;
    g_att[b * DIMM + h * HD + d] = num / den;
}

// ---------------------------------------------------------------------------
extern "C" void kernel_launch(void* const* d_in, const int* in_sizes, int n_in,
                              void* d_out, int out_size)
{
    const float* x  = (const float*)d_in[0];
    const float* fc = (const float*)d_in[1];
    const float* fs = (const float*)d_in[2];
    const float* wq = (const float*)d_in[3];
    const float* wk = (const float*)d_in[4];
    const float* wv = (const float*)d_in[5];
    const float* wo = (const float*)d_in[6];
    const float* ck = (const float*)d_in[7];
    const float* cv = (const float*)d_in[8];
    float* out = (float*)d_out;

    gemm_kernel<0><<<6144 / 16, 128>>>(x, wq, wk, wv, fc, fs, nullptr);
    attn_kernel<<<BB * NKV * NSPLIT, 256>>>(ck, cv);
    reduce_kernel<<<BB * NH, 128>>>();
    gemm_kernel<1><<<4096 / 16, 128>>>(nullptr, wo, nullptr, nullptr, nullptr, nullptr, out);
}